// round 15
// baseline (speedup 1.0000x reference)
#include <cuda_runtime.h>
#include <cuda_fp16.h>
#include <math.h>

#define B_   1024
#define L_   32
#define K_   8
#define G_   8
#define C_   128
#define S_   32
#define GRID_MAIN 296
#define NTILES 64
#define NITEMS (L_ * NTILES)

__device__ unsigned char g_ci[B_ * L_];
__device__ unsigned int g_mask[B_ * G_ * L_];

// ---------- helpers ----------
__device__ __forceinline__ unsigned pack2h(float lo, float hi) {
    unsigned r;
    asm("cvt.rn.f16x2.f32 %0, %1, %2;" : "=r"(r) : "f"(hi), "f"(lo));
    return r;
}
__device__ __forceinline__ __half2 u2h(unsigned u) { return *reinterpret_cast<__half2*>(&u); }
__device__ __forceinline__ unsigned h2u(__half2 h) { return *reinterpret_cast<unsigned*>(&h); }

// packed GN + SiLU: v,mu,inv,w,b all f16x2; returns silu((v-mu)*inv*w+b) packed
__device__ __forceinline__ unsigned gnsilu2(unsigned v, unsigned mu2, unsigned inv2,
                                            unsigned w2, unsigned b2) {
    __half2 x = __hsub2(u2h(v), u2h(mu2));
    x = __hmul2(x, u2h(inv2));
    x = __hfma2(x, u2h(w2), u2h(b2));
    __half2 m = __hmul2(x, __float2half2_rn(0.5f));
    unsigned t;
    asm("tanh.approx.f16x2 %0, %1;" : "=r"(t) : "r"(h2u(m)));
    return h2u(__hfma2(m, u2h(t), m));
}
__device__ __forceinline__ void mma_f16(float* c,
    unsigned a0, unsigned a1, unsigned a2, unsigned a3, unsigned b0, unsigned b1) {
    asm("mma.sync.aligned.m16n8k16.row.col.f32.f16.f16.f32 "
        "{%0,%1,%2,%3},{%4,%5,%6,%7},{%8,%9},{%0,%1,%2,%3};"
        : "+f"(c[0]), "+f"(c[1]), "+f"(c[2]), "+f"(c[3])
        : "r"(a0), "r"(a1), "r"(a2), "r"(a3), "r"(b0), "r"(b1));
}
__device__ __forceinline__ float bitf(unsigned m, int j) {
    return (float)((m >> j) & 1u);
}
__device__ __forceinline__ float2 ldg2(const float* p) {
    return __ldg((const float2*)p);
}
__device__ __forceinline__ void pf_l2(const void* p) {
    asm volatile("prefetch.L2 [%0];" :: "l"(p));
}

// Build the 7 k-block fragment halves for one row (layout per round-12).
__device__ __forceinline__ void build_row(unsigned Mw, bool tfl, int tgt,
                                          const float* zp, const float* zhp,
                                          int d2, unsigned out[7][2]) {
    float2 z0 = ldg2(zp + d2);
    float2 z1 = ldg2(zp + d2 + 8);
    out[0][0] = pack2h(bitf(Mw, d2) * z0.x,      bitf(Mw, d2 + 1) * z0.y);
    out[0][1] = pack2h(bitf(Mw, d2 + 8) * z1.x,  bitf(Mw, d2 + 9) * z1.y);
    float2 z2 = ldg2(zp + d2 + 16);
    float2 z3 = ldg2(zp + d2 + 24);
    out[1][0] = pack2h(bitf(Mw, d2 + 16) * z2.x, bitf(Mw, d2 + 17) * z2.y);
    out[1][1] = pack2h(bitf(Mw, d2 + 24) * z3.x, bitf(Mw, d2 + 25) * z3.y);
    out[2][0] = pack2h(bitf(Mw, d2),      bitf(Mw, d2 + 1));
    out[2][1] = pack2h(bitf(Mw, d2 + 8),  bitf(Mw, d2 + 9));
    out[3][0] = pack2h(bitf(Mw, d2 + 16), bitf(Mw, d2 + 17));
    out[3][1] = pack2h(bitf(Mw, d2 + 24), bitf(Mw, d2 + 25));
    float tv0 = (tfl && tgt == d2)     ? 1.0f : 0.0f;
    float tv1 = (tfl && tgt == d2 + 1) ? 1.0f : 0.0f;
    float2 s0 = ldg2(zhp + d2);
    out[4][0] = pack2h(tv0, tv1);
    out[4][1] = pack2h(s0.x, s0.y);
    float2 s1 = ldg2(zhp + 8 + d2);
    float2 s2 = ldg2(zhp + 16 + d2);
    out[5][0] = pack2h(s1.x, s1.y);
    out[5][1] = pack2h(s2.x, s2.y);
    float2 s3 = ldg2(zhp + 24 + d2);
    out[6][0] = pack2h(s3.x, s3.y);
    out[6][1] = (d2 == 0) ? pack2h(1.0f, 0.0f) : 0u;
}

// ---------- merged prep ----------
__global__ void prep_kernel(const float* __restrict__ tp, const float* __restrict__ ug,
                            const float* __restrict__ th, const float* __restrict__ ga,
                            const float* __restrict__ u_adj, float* __restrict__ out) {
    __shared__ unsigned char sc[L_];
    __shared__ float sep[K_ * K_];
    int b = blockIdx.x, t = threadIdx.x;
    if (t < L_) {
        const float* u = ug + (b * L_ + t) * K_;
        float best = -1e30f; int bi = 0;
#pragma unroll
        for (int k = 0; k < K_; k++) {
            float gum = -logf(-logf(u[k] + 1e-10f) + 1e-10f);
            float v = tp[t * K_ + k] + gum;
            if (v > best) { best = v; bi = k; }
        }
        sc[t] = (unsigned char)bi;
        g_ci[b * L_ + t] = (unsigned char)bi;
    } else if (t >= 64 && t < 128) {
        int e = t - 64;
        float s1 = 1.0f / (1.0f + expf(-th[e]));
        float s2 = 1.0f / (1.0f + expf(-ga[e]));
        sep[e] = s1 * s2;
    }
    if (t == 0) out[b] = 0.0f;
    __syncthreads();
    int g = t >> 5, l = t & 31;
    int cl = sc[l];
    unsigned bits = 0;
#pragma unroll
    for (int cj = 0; cj < K_; cj++) {
        float u = u_adj[((b * G_ + g) * K_ + cj) * K_ + cl];
        bits |= (u < sep[cj * K_ + cl]) ? (1u << cj) : 0u;
    }
    unsigned wv = 0;
#pragma unroll
    for (int j = 0; j < L_; j++) {
        unsigned mj = (bits >> sc[j]) & 1u;
        if (j == l) mj = 0;
        wv |= mj << j;
    }
    g_mask[(b * G_ + g) * L_ + l] = wv;
}

// ---------- smem layout (bytes) ----------
#define OFF_W1    0
#define OFF_W2    40960
#define OFF_WB1H  81920   // uint2[64]: (g1w pair f16x2, g1b pair f16x2)
#define OFF_P2H   82432   // uint2[64]: (g2w pair f16x2, g2b pair f16x2)
#define OFF_B2    82944   // float2[64]: b2 pairs fp32
#define OFF_W3    83456   // float4[64]: (w30_c0, w31_c0, w30_c1, w31_c1)
#define SMEM_BYTES 84480

__global__ __launch_bounds__(256, 2) void main_kernel(
    const float* __restrict__ z_sample, const int* __restrict__ target,
    const float* __restrict__ z_mean,   const float* __restrict__ z_logstd,
    const float* __restrict__ z_shared,
    const float* __restrict__ W1, const float* __restrict__ b1g,
    const float* __restrict__ g1wg, const float* __restrict__ g1bg,
    const float* __restrict__ W2, const float* __restrict__ b2g,
    const float* __restrict__ g2wg, const float* __restrict__ g2bg,
    const float* __restrict__ W3g, const float* __restrict__ b3g,
    const float* __restrict__ tsc, float* __restrict__ out)
{
    extern __shared__ char smem[];
    uint2*  W1u2 = (uint2*)(smem + OFF_W1);
    uint2*  W2u2 = (uint2*)(smem + OFF_W2);
    const uint4* W1q4 = (const uint4*)(smem + OFF_W1);
    const uint4* W2q4 = (const uint4*)(smem + OFF_W2);
    uint2*  sWB1h = (uint2*)(smem + OFF_WB1H);
    uint2*  sP2h  = (uint2*)(smem + OFF_P2H);
    float2* sB2   = (float2*)(smem + OFF_B2);
    float4* sW3   = (float4*)(smem + OFF_W3);

    const int tid = threadIdx.x;
    const int wid = tid >> 5;
    const int lane = tid & 31;
    const int gid = lane >> 2;
    const int t4 = lane & 3;
    const int d2 = t4 * 2;

    const int start = (int)(((long long)blockIdx.x * NITEMS) / GRID_MAIN);
    const int end   = (int)(((long long)(blockIdx.x + 1) * NITEMS) / GRID_MAIN);

    int cur_l = -1;
    float b3_0 = 0.f, b3_1 = 0.f, sc0 = 1.f, sc1 = 1.f, isc0 = 1.f, isc1 = 1.f;

    for (int item = start; item < end; item++) {
        const int l = item >> 6;
        const int tile = item & 63;

        if (l != cur_l) {
            __syncthreads();
            const float* W1g = W1 + l * C_ * 104;
            for (int idx = tid; idx < 128 * 32; idx += 256) {
                int c = idx >> 5, s = idx & 31;
                int kk = s >> 2, tq = s & 3;
                int d0 = kk * 16 + tq * 2, d1 = d0 + 8;
                float w00 = (d0 < 104) ? W1g[c * 104 + d0]
                                       : ((d0 == 104) ? b1g[l * C_ + c] : 0.0f);
                float w01 = (d0 + 1 < 104) ? W1g[c * 104 + d0 + 1] : 0.0f;
                float w10 = (d1 < 104) ? W1g[c * 104 + d1]
                                       : ((d1 == 104) ? b1g[l * C_ + c] : 0.0f);
                float w11 = (d1 + 1 < 104) ? W1g[c * 104 + d1 + 1] : 0.0f;
                W1u2[c * 40 + (kk >> 1) * 8 + tq * 2 + (kk & 1)] =
                    make_uint2(pack2h(w00, w01), pack2h(w10, w11));
            }
            const float* W2g = W2 + l * C_ * C_;
            for (int idx = tid; idx < 128 * 32; idx += 256) {
                int c = idx >> 5, s = idx & 31;
                int kk = s >> 2, tq = s & 3;
                int d0 = kk * 16 + tq * 2, d1 = d0 + 8;
                W2u2[c * 40 + (kk >> 1) * 8 + tq * 2 + (kk & 1)] =
                    make_uint2(pack2h(W2g[c * C_ + d0], W2g[c * C_ + d0 + 1]),
                               pack2h(W2g[c * C_ + d1], W2g[c * C_ + d1 + 1]));
            }
            if (tid < 64) {
                int c0 = 2 * tid;
                sWB1h[tid] = make_uint2(pack2h(g1wg[l * C_ + c0], g1wg[l * C_ + c0 + 1]),
                                        pack2h(g1bg[l * C_ + c0], g1bg[l * C_ + c0 + 1]));
                sP2h[tid]  = make_uint2(pack2h(g2wg[l * C_ + c0], g2wg[l * C_ + c0 + 1]),
                                        pack2h(g2bg[l * C_ + c0], g2bg[l * C_ + c0 + 1]));
                sB2[tid]   = make_float2(b2g[l * C_ + c0], b2g[l * C_ + c0 + 1]);
                sW3[tid]   = make_float4(W3g[l * 2 * C_ + c0],     W3g[l * 2 * C_ + C_ + c0],
                                         W3g[l * 2 * C_ + c0 + 1], W3g[l * 2 * C_ + C_ + c0 + 1]);
            }
            b3_0 = b3g[l * 2]; b3_1 = b3g[l * 2 + 1];
            sc0 = __expf(tsc[l * 2]); sc1 = __expf(tsc[l * 2 + 1]);
            isc0 = 1.0f / sc0; isc1 = 1.0f / sc1;
            __syncthreads();
            cur_l = l;
        }

        // per-thread rows: r0 = wid*16+gid (batch b0), r1 = r0+8 (batch b1)
        const int grow0 = tile * 128 + wid * 16 + gid;
        const int grow1 = grow0 + 8;
        const int b0i = grow0 >> 3, b1i = grow1 >> 3;
        const unsigned Mw0 = __ldg(&g_mask[grow0 * L_ + l]);
        const unsigned Mw1 = __ldg(&g_mask[grow1 * L_ + l]);
        const int tgt0 = __ldg(&target[b0i]), tgt1 = __ldg(&target[b1i]);
        const bool tf0 = (g_ci[b0i * L_ + l] == tgt0);
        const bool tf1 = (g_ci[b1i * L_ + l] == tgt1);

        // ---- build A1 fragments from global (L2-hot) ----
        unsigned Ah[7][4];
        {
            unsigned rA[7][2], rB[7][2];
            build_row(Mw0, tf0, tgt0, z_sample + b0i * L_, z_shared + b0i * S_, d2, rA);
            build_row(Mw1, tf1, tgt1, z_sample + b1i * L_, z_shared + b1i * S_, d2, rB);
#pragma unroll
            for (int kk = 0; kk < 7; kk++) {
                Ah[kk][0] = rA[kk][0];
                Ah[kk][1] = rB[kk][0];
                Ah[kk][2] = rA[kk][1];
                Ah[kk][3] = rB[kk][1];
            }
        }

        // ---- prefetch next item's inputs into L2 (overlaps with MMAs) ----
        if (item + 1 < end && lane < 16) {
            const int ntile = (item + 1) & 63;
            const int nl = (item + 1) >> 6;
            const int nb = ntile * 16 + lane;              // 16 batch rows of next tile
            pf_l2(z_sample + nb * L_);
            pf_l2(z_shared + nb * S_);
            pf_l2(&g_mask[(ntile * 128 + wid * 16 + lane) * L_ + nl]);
        }

        // ---- MMA1 (bias folded into W1) ----
        float acc[16][4];
#pragma unroll
        for (int nt = 0; nt < 16; nt++)
#pragma unroll
            for (int i = 0; i < 4; i++) acc[nt][i] = 0.0f;

#pragma unroll
        for (int nt = 0; nt < 16; nt++) {
            const uint4* bp = W1q4 + (nt * 8 + gid) * 20 + t4;
#pragma unroll
            for (int j = 0; j < 4; j++) {
                uint4 bq = bp[j * 4];
                mma_f16(acc[nt], Ah[2*j][0], Ah[2*j][1], Ah[2*j][2], Ah[2*j][3], bq.x, bq.y);
                if (j < 3)
                    mma_f16(acc[nt], Ah[2*j+1][0], Ah[2*j+1][1], Ah[2*j+1][2], Ah[2*j+1][3], bq.z, bq.w);
            }
        }

        // ---- GN1 stats (fp32) ----
        float s0 = 0.f, q0 = 0.f, s1 = 0.f, q1 = 0.f;
#pragma unroll
        for (int nt = 0; nt < 16; nt++) {
            s0 += acc[nt][0] + acc[nt][1];
            q0 += acc[nt][0] * acc[nt][0] + acc[nt][1] * acc[nt][1];
            s1 += acc[nt][2] + acc[nt][3];
            q1 += acc[nt][2] * acc[nt][2] + acc[nt][3] * acc[nt][3];
        }
#pragma unroll
        for (int o = 1; o <= 2; o <<= 1) {
            s0 += __shfl_xor_sync(0xffffffffu, s0, o);
            q0 += __shfl_xor_sync(0xffffffffu, q0, o);
            s1 += __shfl_xor_sync(0xffffffffu, s1, o);
            q1 += __shfl_xor_sync(0xffffffffu, q1, o);
        }
        float mu0 = s0 * (1.0f / 128.0f);
        float inv0 = rsqrtf(q0 * (1.0f / 128.0f) - mu0 * mu0 + 1e-5f);
        float mu1 = s1 * (1.0f / 128.0f);
        float inv1 = rsqrtf(q1 * (1.0f / 128.0f) - mu1 * mu1 + 1e-5f);

        // ---- GN1 + SiLU in packed f16x2 -> A2 fragments ----
        unsigned mu2_0 = pack2h(mu0, mu0), mu2_1 = pack2h(mu1, mu1);
        unsigned iv2_0 = pack2h(inv0, inv0), iv2_1 = pack2h(inv1, inv1);
        unsigned A2h[8][4];
#pragma unroll
        for (int kk = 0; kk < 8; kk++) {
            int nt0 = 2 * kk, nt1 = 2 * kk + 1;
            uint2 wb0 = sWB1h[nt0 * 4 + t4];
            uint2 wb1 = sWB1h[nt1 * 4 + t4];
            A2h[kk][0] = gnsilu2(pack2h(acc[nt0][0], acc[nt0][1]), mu2_0, iv2_0, wb0.x, wb0.y);
            A2h[kk][1] = gnsilu2(pack2h(acc[nt0][2], acc[nt0][3]), mu2_1, iv2_1, wb0.x, wb0.y);
            A2h[kk][2] = gnsilu2(pack2h(acc[nt1][0], acc[nt1][1]), mu2_0, iv2_0, wb1.x, wb1.y);
            A2h[kk][3] = gnsilu2(pack2h(acc[nt1][2], acc[nt1][3]), mu2_1, iv2_1, wb1.x, wb1.y);
        }

        // ---- MMA2 (acc initialized with b2 -> bias add is free) ----
#pragma unroll
        for (int nt = 0; nt < 16; nt++) {
            float2 bb = sB2[nt * 4 + t4];
            acc[nt][0] = bb.x; acc[nt][1] = bb.y;
            acc[nt][2] = bb.x; acc[nt][3] = bb.y;
        }

#pragma unroll
        for (int nt = 0; nt < 16; nt++) {
            const uint4* bp = W2q4 + (nt * 8 + gid) * 20 + t4;
#pragma unroll
            for (int j = 0; j < 4; j++) {
                uint4 bq = bp[j * 4];
                mma_f16(acc[nt], A2h[2*j][0], A2h[2*j][1], A2h[2*j][2], A2h[2*j][3], bq.x, bq.y);
                mma_f16(acc[nt], A2h[2*j+1][0], A2h[2*j+1][1], A2h[2*j+1][2], A2h[2*j+1][3], bq.z, bq.w);
            }
        }

        // ---- GN2 stats (fp32) ----
        s0 = 0.f; q0 = 0.f; s1 = 0.f; q1 = 0.f;
#pragma unroll
        for (int nt = 0; nt < 16; nt++) {
            s0 += acc[nt][0] + acc[nt][1];
            q0 += acc[nt][0] * acc[nt][0] + acc[nt][1] * acc[nt][1];
            s1 += acc[nt][2] + acc[nt][3];
            q1 += acc[nt][2] * acc[nt][2] + acc[nt][3] * acc[nt][3];
        }
#pragma unroll
        for (int o = 1; o <= 2; o <<= 1) {
            s0 += __shfl_xor_sync(0xffffffffu, s0, o);
            q0 += __shfl_xor_sync(0xffffffffu, q0, o);
            s1 += __shfl_xor_sync(0xffffffffu, s1, o);
            q1 += __shfl_xor_sync(0xffffffffu, q1, o);
        }
        mu0 = s0 * (1.0f / 128.0f);
        inv0 = rsqrtf(q0 * (1.0f / 128.0f) - mu0 * mu0 + 1e-5f);
        mu1 = s1 * (1.0f / 128.0f);
        inv1 = rsqrtf(q1 * (1.0f / 128.0f) - mu1 * mu1 + 1e-5f);
        mu2_0 = pack2h(mu0, mu0); mu2_1 = pack2h(mu1, mu1);
        iv2_0 = pack2h(inv0, inv0); iv2_1 = pack2h(inv1, inv1);

        // ---- GN2 + SiLU (f16x2) + W3 dot (fp32) + KL ----
        float p00 = 0.f, p10 = 0.f, p01 = 0.f, p11 = 0.f;
#pragma unroll
        for (int nt = 0; nt < 16; nt++) {
            uint2 wb = sP2h[nt * 4 + t4];
            float4 w3 = sW3[nt * 4 + t4];  // (w30_c0, w31_c0, w30_c1, w31_c1)
            float2 ha = __half22float2(u2h(
                gnsilu2(pack2h(acc[nt][0], acc[nt][1]), mu2_0, iv2_0, wb.x, wb.y)));
            float2 hb = __half22float2(u2h(
                gnsilu2(pack2h(acc[nt][2], acc[nt][3]), mu2_1, iv2_1, wb.x, wb.y)));
            p00 += ha.x * w3.x + ha.y * w3.z;
            p10 += ha.x * w3.y + ha.y * w3.w;
            p01 += hb.x * w3.x + hb.y * w3.z;
            p11 += hb.x * w3.y + hb.y * w3.w;
        }
#pragma unroll
        for (int o = 1; o <= 2; o <<= 1) {
            p00 += __shfl_xor_sync(0xffffffffu, p00, o);
            p10 += __shfl_xor_sync(0xffffffffu, p10, o);
            p01 += __shfl_xor_sync(0xffffffffu, p01, o);
            p11 += __shfl_xor_sync(0xffffffffu, p11, o);
        }
        if (t4 == 0) {
            {
                float o0 = p00 + b3_0, o1 = p10 + b3_1;
                float pm = tanhf(o0 * isc0) * sc0;
                float pl = tanhf(o1 * isc1) * sc1;
                float zl = z_logstd[b0i * L_ + l], zmn = z_mean[b0i * L_ + l];
                float dmu = zmn - pm;
                float kld = pl - zl + (__expf(2.0f * zl) + dmu * dmu) * 0.5f * __expf(-2.0f * pl) - 0.5f;
                atomicAdd(out + b0i, kld * 0.125f);
            }
            {
                float o0 = p01 + b3_0, o1 = p11 + b3_1;
                float pm = tanhf(o0 * isc0) * sc0;
                float pl = tanhf(o1 * isc1) * sc1;
                float zl = z_logstd[b1i * L_ + l], zmn = z_mean[b1i * L_ + l];
                float dmu = zmn - pm;
                float kld = pl - zl + (__expf(2.0f * zl) + dmu * dmu) * 0.5f * __expf(-2.0f * pl) - 0.5f;
                atomicAdd(out + b1i, kld * 0.125f);
            }
        }
    }
}

extern "C" void kernel_launch(void* const* d_in, const int* in_sizes, int n_in,
                              void* d_out, int out_size) {
    const float* z_sample      = (const float*)d_in[0];
    const int*   target        = (const int*)  d_in[1];
    const float* z_mean        = (const float*)d_in[2];
    const float* z_logstd      = (const float*)d_in[3];
    const float* z_shared      = (const float*)d_in[4];
    const float* u_gumbel      = (const float*)d_in[5];
    const float* u_adj         = (const float*)d_in[6];
    const float* target_params = (const float*)d_in[7];
    const float* enco_theta    = (const float*)d_in[8];
    const float* enco_gamma    = (const float*)d_in[9];
    const float* W1            = (const float*)d_in[10];
    const float* b1            = (const float*)d_in[11];
    const float* gn1_w         = (const float*)d_in[12];
    const float* gn1_b         = (const float*)d_in[13];
    const float* W2            = (const float*)d_in[14];
    const float* b2            = (const float*)d_in[15];
    const float* gn2_w         = (const float*)d_in[16];
    const float* gn2_b         = (const float*)d_in[17];
    const float* W3            = (const float*)d_in[18];
    const float* b3            = (const float*)d_in[19];
    const float* tanh_scale    = (const float*)d_in[20];
    float* out = (float*)d_out;

    prep_kernel<<<B_, 256>>>(target_params, u_gumbel, enco_theta, enco_gamma, u_adj, out);

    cudaFuncSetAttribute(main_kernel, cudaFuncAttributeMaxDynamicSharedMemorySize, SMEM_BYTES);
    main_kernel<<<GRID_MAIN, 256, SMEM_BYTES>>>(
        z_sample, target, z_mean, z_logstd, z_shared,
        W1, b1, gn1_w, gn1_b, W2, b2, gn2_w, gn2_b, W3, b3, tanh_scale, out);
}

// round 16
// speedup vs baseline: 1.0070x; 1.0070x over previous
#include <cuda_runtime.h>
#include <cuda_fp16.h>
#include <math.h>

#define B_   1024
#define L_   32
#define K_   8
#define G_   8
#define C_   128
#define S_   32
#define GRID_MAIN 296
#define NTILES 64
#define NITEMS (L_ * NTILES)

__device__ unsigned char g_ci[B_ * L_];
__device__ unsigned int g_mask[B_ * G_ * L_];

// ---------- helpers ----------
__device__ __forceinline__ unsigned pack2h(float lo, float hi) {
    unsigned r;
    asm("cvt.rn.f16x2.f32 %0, %1, %2;" : "=r"(r) : "f"(hi), "f"(lo));
    return r;
}
__device__ __forceinline__ __half2 u2h(unsigned u) { return *reinterpret_cast<__half2*>(&u); }
__device__ __forceinline__ unsigned h2u(__half2 h) { return *reinterpret_cast<unsigned*>(&h); }

__device__ __forceinline__ float tanh_fast(float x) {
    float xc = fminf(fmaxf(x, -15.0f), 15.0f);
    float e = __expf(2.0f * xc);
    return __fdividef(e - 1.0f, e + 1.0f);
}

// packed GN + SiLU: v,mu,inv,w,b all f16x2; returns silu((v-mu)*inv*w+b) packed
__device__ __forceinline__ unsigned gnsilu2(unsigned v, unsigned mu2, unsigned inv2,
                                            unsigned w2, unsigned b2) {
    __half2 x = __hsub2(u2h(v), u2h(mu2));
    x = __hmul2(x, u2h(inv2));
    x = __hfma2(x, u2h(w2), u2h(b2));
    __half2 m = __hmul2(x, __float2half2_rn(0.5f));
    unsigned t;
    asm("tanh.approx.f16x2 %0, %1;" : "=r"(t) : "r"(h2u(m)));
    return h2u(__hfma2(m, u2h(t), m));
}
__device__ __forceinline__ void mma_f16(float* c,
    unsigned a0, unsigned a1, unsigned a2, unsigned a3, unsigned b0, unsigned b1) {
    asm("mma.sync.aligned.m16n8k16.row.col.f32.f16.f16.f32 "
        "{%0,%1,%2,%3},{%4,%5,%6,%7},{%8,%9},{%0,%1,%2,%3};"
        : "+f"(c[0]), "+f"(c[1]), "+f"(c[2]), "+f"(c[3])
        : "r"(a0), "r"(a1), "r"(a2), "r"(a3), "r"(b0), "r"(b1));
}
__device__ __forceinline__ float bitf(unsigned m, int j) {
    return (float)((m >> j) & 1u);
}
__device__ __forceinline__ float2 ldg2(const float* p) {
    return __ldg((const float2*)p);
}

// Build the 7 k-block fragment halves for one row (layout per round-12).
__device__ __forceinline__ void build_row(unsigned Mw, bool tfl, int tgt,
                                          const float* zp, const float* zhp,
                                          int d2, unsigned out[7][2]) {
    float2 z0 = ldg2(zp + d2);
    float2 z1 = ldg2(zp + d2 + 8);
    out[0][0] = pack2h(bitf(Mw, d2) * z0.x,      bitf(Mw, d2 + 1) * z0.y);
    out[0][1] = pack2h(bitf(Mw, d2 + 8) * z1.x,  bitf(Mw, d2 + 9) * z1.y);
    float2 z2 = ldg2(zp + d2 + 16);
    float2 z3 = ldg2(zp + d2 + 24);
    out[1][0] = pack2h(bitf(Mw, d2 + 16) * z2.x, bitf(Mw, d2 + 17) * z2.y);
    out[1][1] = pack2h(bitf(Mw, d2 + 24) * z3.x, bitf(Mw, d2 + 25) * z3.y);
    out[2][0] = pack2h(bitf(Mw, d2),      bitf(Mw, d2 + 1));
    out[2][1] = pack2h(bitf(Mw, d2 + 8),  bitf(Mw, d2 + 9));
    out[3][0] = pack2h(bitf(Mw, d2 + 16), bitf(Mw, d2 + 17));
    out[3][1] = pack2h(bitf(Mw, d2 + 24), bitf(Mw, d2 + 25));
    float tv0 = (tfl && tgt == d2)     ? 1.0f : 0.0f;
    float tv1 = (tfl && tgt == d2 + 1) ? 1.0f : 0.0f;
    float2 s0 = ldg2(zhp + d2);
    out[4][0] = pack2h(tv0, tv1);
    out[4][1] = pack2h(s0.x, s0.y);
    float2 s1 = ldg2(zhp + 8 + d2);
    float2 s2 = ldg2(zhp + 16 + d2);
    out[5][0] = pack2h(s1.x, s1.y);
    out[5][1] = pack2h(s2.x, s2.y);
    float2 s3 = ldg2(zhp + 24 + d2);
    out[6][0] = pack2h(s3.x, s3.y);
    out[6][1] = (d2 == 0) ? pack2h(1.0f, 0.0f) : 0u;
}

// ---------- merged prep ----------
__global__ void prep_kernel(const float* __restrict__ tp, const float* __restrict__ ug,
                            const float* __restrict__ th, const float* __restrict__ ga,
                            const float* __restrict__ u_adj, float* __restrict__ out) {
    __shared__ unsigned char sc[L_];
    __shared__ float sep[K_ * K_];
    int b = blockIdx.x, t = threadIdx.x;
    if (t < L_) {
        const float* u = ug + (b * L_ + t) * K_;
        float best = -1e30f; int bi = 0;
#pragma unroll
        for (int k = 0; k < K_; k++) {
            float gum = -logf(-logf(u[k] + 1e-10f) + 1e-10f);
            float v = tp[t * K_ + k] + gum;
            if (v > best) { best = v; bi = k; }
        }
        sc[t] = (unsigned char)bi;
        g_ci[b * L_ + t] = (unsigned char)bi;
    } else if (t >= 64 && t < 128) {
        int e = t - 64;
        float s1 = 1.0f / (1.0f + expf(-th[e]));
        float s2 = 1.0f / (1.0f + expf(-ga[e]));
        sep[e] = s1 * s2;
    }
    if (t == 0) out[b] = 0.0f;
    __syncthreads();
    int g = t >> 5, l = t & 31;
    int cl = sc[l];
    unsigned bits = 0;
#pragma unroll
    for (int cj = 0; cj < K_; cj++) {
        float u = u_adj[((b * G_ + g) * K_ + cj) * K_ + cl];
        bits |= (u < sep[cj * K_ + cl]) ? (1u << cj) : 0u;
    }
    unsigned wv = 0;
#pragma unroll
    for (int j = 0; j < L_; j++) {
        unsigned mj = (bits >> sc[j]) & 1u;
        if (j == l) mj = 0;
        wv |= mj << j;
    }
    g_mask[(b * G_ + g) * L_ + l] = wv;
}

// ---------- smem layout (bytes) ----------
#define OFF_W1    0
#define OFF_W2    40960
#define OFF_WB1H  81920   // uint2[64]: (g1w pair f16x2, g1b pair f16x2)
#define OFF_P2H   82432   // uint2[64]: (g2w pair f16x2, g2b pair f16x2)
#define OFF_B2    82944   // float2[64]: b2 pairs fp32
#define OFF_W3    83456   // float4[64]: (w30_c0, w31_c0, w30_c1, w31_c1)
#define SMEM_BYTES 84480

__global__ __launch_bounds__(256, 2) void main_kernel(
    const float* __restrict__ z_sample, const int* __restrict__ target,
    const float* __restrict__ z_mean,   const float* __restrict__ z_logstd,
    const float* __restrict__ z_shared,
    const float* __restrict__ W1, const float* __restrict__ b1g,
    const float* __restrict__ g1wg, const float* __restrict__ g1bg,
    const float* __restrict__ W2, const float* __restrict__ b2g,
    const float* __restrict__ g2wg, const float* __restrict__ g2bg,
    const float* __restrict__ W3g, const float* __restrict__ b3g,
    const float* __restrict__ tsc, float* __restrict__ out)
{
    extern __shared__ char smem[];
    uint2*  W1u2 = (uint2*)(smem + OFF_W1);
    uint2*  W2u2 = (uint2*)(smem + OFF_W2);
    const uint4* W1q4 = (const uint4*)(smem + OFF_W1);
    const uint4* W2q4 = (const uint4*)(smem + OFF_W2);
    uint2*  sWB1h = (uint2*)(smem + OFF_WB1H);
    uint2*  sP2h  = (uint2*)(smem + OFF_P2H);
    float2* sB2   = (float2*)(smem + OFF_B2);
    float4* sW3   = (float4*)(smem + OFF_W3);

    const int tid = threadIdx.x;
    const int wid = tid >> 5;
    const int lane = tid & 31;
    const int gid = lane >> 2;
    const int t4 = lane & 3;
    const int d2 = t4 * 2;

    const int start = (int)(((long long)blockIdx.x * NITEMS) / GRID_MAIN);
    const int end   = (int)(((long long)(blockIdx.x + 1) * NITEMS) / GRID_MAIN);

    int cur_l = -1;
    float b3_0 = 0.f, b3_1 = 0.f, sc0 = 1.f, sc1 = 1.f, isc0 = 1.f, isc1 = 1.f;

    for (int item = start; item < end; item++) {
        const int l = item >> 6;
        const int tile = item & 63;

        if (l != cur_l) {
            __syncthreads();
            const float* W1g = W1 + l * C_ * 104;
            for (int idx = tid; idx < 128 * 32; idx += 256) {
                int c = idx >> 5, s = idx & 31;
                int kk = s >> 2, tq = s & 3;
                int d0 = kk * 16 + tq * 2, d1 = d0 + 8;
                float w00 = (d0 < 104) ? W1g[c * 104 + d0]
                                       : ((d0 == 104) ? b1g[l * C_ + c] : 0.0f);
                float w01 = (d0 + 1 < 104) ? W1g[c * 104 + d0 + 1] : 0.0f;
                float w10 = (d1 < 104) ? W1g[c * 104 + d1]
                                       : ((d1 == 104) ? b1g[l * C_ + c] : 0.0f);
                float w11 = (d1 + 1 < 104) ? W1g[c * 104 + d1 + 1] : 0.0f;
                W1u2[c * 40 + (kk >> 1) * 8 + tq * 2 + (kk & 1)] =
                    make_uint2(pack2h(w00, w01), pack2h(w10, w11));
            }
            const float* W2g = W2 + l * C_ * C_;
            for (int idx = tid; idx < 128 * 32; idx += 256) {
                int c = idx >> 5, s = idx & 31;
                int kk = s >> 2, tq = s & 3;
                int d0 = kk * 16 + tq * 2, d1 = d0 + 8;
                W2u2[c * 40 + (kk >> 1) * 8 + tq * 2 + (kk & 1)] =
                    make_uint2(pack2h(W2g[c * C_ + d0], W2g[c * C_ + d0 + 1]),
                               pack2h(W2g[c * C_ + d1], W2g[c * C_ + d1 + 1]));
            }
            if (tid < 64) {
                int c0 = 2 * tid;
                sWB1h[tid] = make_uint2(pack2h(g1wg[l * C_ + c0], g1wg[l * C_ + c0 + 1]),
                                        pack2h(g1bg[l * C_ + c0], g1bg[l * C_ + c0 + 1]));
                sP2h[tid]  = make_uint2(pack2h(g2wg[l * C_ + c0], g2wg[l * C_ + c0 + 1]),
                                        pack2h(g2bg[l * C_ + c0], g2bg[l * C_ + c0 + 1]));
                sB2[tid]   = make_float2(b2g[l * C_ + c0], b2g[l * C_ + c0 + 1]);
                sW3[tid]   = make_float4(W3g[l * 2 * C_ + c0],     W3g[l * 2 * C_ + C_ + c0],
                                         W3g[l * 2 * C_ + c0 + 1], W3g[l * 2 * C_ + C_ + c0 + 1]);
            }
            b3_0 = b3g[l * 2]; b3_1 = b3g[l * 2 + 1];
            sc0 = __expf(tsc[l * 2]); sc1 = __expf(tsc[l * 2 + 1]);
            isc0 = 1.0f / sc0; isc1 = 1.0f / sc1;
            __syncthreads();
            cur_l = l;
        }

        // per-thread rows: r0 = wid*16+gid (batch b0), r1 = r0+8 (batch b1)
        const int grow0 = tile * 128 + wid * 16 + gid;
        const int grow1 = grow0 + 8;
        const int b0i = grow0 >> 3, b1i = grow1 >> 3;
        const unsigned Mw0 = __ldg(&g_mask[grow0 * L_ + l]);
        const unsigned Mw1 = __ldg(&g_mask[grow1 * L_ + l]);
        const int tgt0 = __ldg(&target[b0i]), tgt1 = __ldg(&target[b1i]);
        const bool tf0 = (g_ci[b0i * L_ + l] == tgt0);
        const bool tf1 = (g_ci[b1i * L_ + l] == tgt1);

        // ---- build A1 fragments from global (L2-hot) ----
        unsigned Ah[7][4];
        {
            unsigned rA[7][2], rB[7][2];
            build_row(Mw0, tf0, tgt0, z_sample + b0i * L_, z_shared + b0i * S_, d2, rA);
            build_row(Mw1, tf1, tgt1, z_sample + b1i * L_, z_shared + b1i * S_, d2, rB);
#pragma unroll
            for (int kk = 0; kk < 7; kk++) {
                Ah[kk][0] = rA[kk][0];
                Ah[kk][1] = rB[kk][0];
                Ah[kk][2] = rA[kk][1];
                Ah[kk][3] = rB[kk][1];
            }
        }

        // ---- MMA1 (bias folded into W1) ----
        float acc[16][4];
#pragma unroll
        for (int nt = 0; nt < 16; nt++)
#pragma unroll
            for (int i = 0; i < 4; i++) acc[nt][i] = 0.0f;

#pragma unroll
        for (int nt = 0; nt < 16; nt++) {
            const uint4* bp = W1q4 + (nt * 8 + gid) * 20 + t4;
#pragma unroll
            for (int j = 0; j < 4; j++) {
                uint4 bq = bp[j * 4];
                mma_f16(acc[nt], Ah[2*j][0], Ah[2*j][1], Ah[2*j][2], Ah[2*j][3], bq.x, bq.y);
                if (j < 3)
                    mma_f16(acc[nt], Ah[2*j+1][0], Ah[2*j+1][1], Ah[2*j+1][2], Ah[2*j+1][3], bq.z, bq.w);
            }
        }

        // ---- GN1 stats (fp32) ----
        float s0 = 0.f, q0 = 0.f, s1 = 0.f, q1 = 0.f;
#pragma unroll
        for (int nt = 0; nt < 16; nt++) {
            s0 += acc[nt][0] + acc[nt][1];
            q0 += acc[nt][0] * acc[nt][0] + acc[nt][1] * acc[nt][1];
            s1 += acc[nt][2] + acc[nt][3];
            q1 += acc[nt][2] * acc[nt][2] + acc[nt][3] * acc[nt][3];
        }
#pragma unroll
        for (int o = 1; o <= 2; o <<= 1) {
            s0 += __shfl_xor_sync(0xffffffffu, s0, o);
            q0 += __shfl_xor_sync(0xffffffffu, q0, o);
            s1 += __shfl_xor_sync(0xffffffffu, s1, o);
            q1 += __shfl_xor_sync(0xffffffffu, q1, o);
        }
        float mu0 = s0 * (1.0f / 128.0f);
        float inv0 = rsqrtf(q0 * (1.0f / 128.0f) - mu0 * mu0 + 1e-5f);
        float mu1 = s1 * (1.0f / 128.0f);
        float inv1 = rsqrtf(q1 * (1.0f / 128.0f) - mu1 * mu1 + 1e-5f);

        // ---- GN1 + SiLU in packed f16x2 -> A2 fragments ----
        unsigned mu2_0 = pack2h(mu0, mu0), mu2_1 = pack2h(mu1, mu1);
        unsigned iv2_0 = pack2h(inv0, inv0), iv2_1 = pack2h(inv1, inv1);
        unsigned A2h[8][4];
#pragma unroll
        for (int kk = 0; kk < 8; kk++) {
            int nt0 = 2 * kk, nt1 = 2 * kk + 1;
            uint2 wb0 = sWB1h[nt0 * 4 + t4];
            uint2 wb1 = sWB1h[nt1 * 4 + t4];
            A2h[kk][0] = gnsilu2(pack2h(acc[nt0][0], acc[nt0][1]), mu2_0, iv2_0, wb0.x, wb0.y);
            A2h[kk][1] = gnsilu2(pack2h(acc[nt0][2], acc[nt0][3]), mu2_1, iv2_1, wb0.x, wb0.y);
            A2h[kk][2] = gnsilu2(pack2h(acc[nt1][0], acc[nt1][1]), mu2_0, iv2_0, wb1.x, wb1.y);
            A2h[kk][3] = gnsilu2(pack2h(acc[nt1][2], acc[nt1][3]), mu2_1, iv2_1, wb1.x, wb1.y);
        }

        // ---- MMA2 (acc initialized with b2 -> bias add is free) ----
#pragma unroll
        for (int nt = 0; nt < 16; nt++) {
            float2 bb = sB2[nt * 4 + t4];
            acc[nt][0] = bb.x; acc[nt][1] = bb.y;
            acc[nt][2] = bb.x; acc[nt][3] = bb.y;
        }

#pragma unroll
        for (int nt = 0; nt < 16; nt++) {
            const uint4* bp = W2q4 + (nt * 8 + gid) * 20 + t4;
#pragma unroll
            for (int j = 0; j < 4; j++) {
                uint4 bq = bp[j * 4];
                mma_f16(acc[nt], A2h[2*j][0], A2h[2*j][1], A2h[2*j][2], A2h[2*j][3], bq.x, bq.y);
                mma_f16(acc[nt], A2h[2*j+1][0], A2h[2*j+1][1], A2h[2*j+1][2], A2h[2*j+1][3], bq.z, bq.w);
            }
        }

        // ---- GN2 stats (fp32) ----
        s0 = 0.f; q0 = 0.f; s1 = 0.f; q1 = 0.f;
#pragma unroll
        for (int nt = 0; nt < 16; nt++) {
            s0 += acc[nt][0] + acc[nt][1];
            q0 += acc[nt][0] * acc[nt][0] + acc[nt][1] * acc[nt][1];
            s1 += acc[nt][2] + acc[nt][3];
            q1 += acc[nt][2] * acc[nt][2] + acc[nt][3] * acc[nt][3];
        }
#pragma unroll
        for (int o = 1; o <= 2; o <<= 1) {
            s0 += __shfl_xor_sync(0xffffffffu, s0, o);
            q0 += __shfl_xor_sync(0xffffffffu, q0, o);
            s1 += __shfl_xor_sync(0xffffffffu, s1, o);
            q1 += __shfl_xor_sync(0xffffffffu, q1, o);
        }
        mu0 = s0 * (1.0f / 128.0f);
        inv0 = rsqrtf(q0 * (1.0f / 128.0f) - mu0 * mu0 + 1e-5f);
        mu1 = s1 * (1.0f / 128.0f);
        inv1 = rsqrtf(q1 * (1.0f / 128.0f) - mu1 * mu1 + 1e-5f);
        mu2_0 = pack2h(mu0, mu0); mu2_1 = pack2h(mu1, mu1);
        iv2_0 = pack2h(inv0, inv0); iv2_1 = pack2h(inv1, inv1);

        // ---- GN2 + SiLU (f16x2) + W3 dot (fp32) ----
        float p00 = 0.f, p10 = 0.f, p01 = 0.f, p11 = 0.f;
#pragma unroll
        for (int nt = 0; nt < 16; nt++) {
            uint2 wb = sP2h[nt * 4 + t4];
            float4 w3 = sW3[nt * 4 + t4];  // (w30_c0, w31_c0, w30_c1, w31_c1)
            float2 ha = __half22float2(u2h(
                gnsilu2(pack2h(acc[nt][0], acc[nt][1]), mu2_0, iv2_0, wb.x, wb.y)));
            float2 hb = __half22float2(u2h(
                gnsilu2(pack2h(acc[nt][2], acc[nt][3]), mu2_1, iv2_1, wb.x, wb.y)));
            p00 += ha.x * w3.x + ha.y * w3.z;
            p10 += ha.x * w3.y + ha.y * w3.w;
            p01 += hb.x * w3.x + hb.y * w3.z;
            p11 += hb.x * w3.y + hb.y * w3.w;
        }
#pragma unroll
        for (int o = 1; o <= 2; o <<= 1) {
            p00 += __shfl_xor_sync(0xffffffffu, p00, o);
            p10 += __shfl_xor_sync(0xffffffffu, p10, o);
            p01 += __shfl_xor_sync(0xffffffffu, p01, o);
            p11 += __shfl_xor_sync(0xffffffffu, p11, o);
        }

        // ---- KL on all lanes (quad-uniform), reduce over 8 graphs, 1 atomic/b ----
        float kld0, kld1;
        {
            float zl = z_logstd[b0i * L_ + l], zmn = z_mean[b0i * L_ + l];
            float o0 = p00 + b3_0, o1 = p10 + b3_1;
            float pm = tanh_fast(o0 * isc0) * sc0;
            float pl = tanh_fast(o1 * isc1) * sc1;
            float dmu = zmn - pm;
            kld0 = pl - zl + (__expf(2.0f * zl) + dmu * dmu) * 0.5f * __expf(-2.0f * pl) - 0.5f;
        }
        {
            float zl = z_logstd[b1i * L_ + l], zmn = z_mean[b1i * L_ + l];
            float o0 = p01 + b3_0, o1 = p11 + b3_1;
            float pm = tanh_fast(o0 * isc0) * sc0;
            float pl = tanh_fast(o1 * isc1) * sc1;
            float dmu = zmn - pm;
            kld1 = pl - zl + (__expf(2.0f * zl) + dmu * dmu) * 0.5f * __expf(-2.0f * pl) - 0.5f;
        }
#pragma unroll
        for (int o = 4; o <= 16; o <<= 1) {
            kld0 += __shfl_xor_sync(0xffffffffu, kld0, o);
            kld1 += __shfl_xor_sync(0xffffffffu, kld1, o);
        }
        if (lane == 0) {
            atomicAdd(out + b0i, kld0 * 0.125f);
            atomicAdd(out + b1i, kld1 * 0.125f);
        }
    }
}

extern "C" void kernel_launch(void* const* d_in, const int* in_sizes, int n_in,
                              void* d_out, int out_size) {
    const float* z_sample      = (const float*)d_in[0];
    const int*   target        = (const int*)  d_in[1];
    const float* z_mean        = (const float*)d_in[2];
    const float* z_logstd      = (const float*)d_in[3];
    const float* z_shared      = (const float*)d_in[4];
    const float* u_gumbel      = (const float*)d_in[5];
    const float* u_adj         = (const float*)d_in[6];
    const float* target_params = (const float*)d_in[7];
    const float* enco_theta    = (const float*)d_in[8];
    const float* enco_gamma    = (const float*)d_in[9];
    const float* W1            = (const float*)d_in[10];
    const float* b1            = (const float*)d_in[11];
    const float* gn1_w         = (const float*)d_in[12];
    const float* gn1_b         = (const float*)d_in[13];
    const float* W2            = (const float*)d_in[14];
    const float* b2            = (const float*)d_in[15];
    const float* gn2_w         = (const float*)d_in[16];
    const float* gn2_b         = (const float*)d_in[17];
    const float* W3            = (const float*)d_in[18];
    const float* b3            = (const float*)d_in[19];
    const float* tanh_scale    = (const float*)d_in[20];
    float* out = (float*)d_out;

    prep_kernel<<<B_, 256>>>(target_params, u_gumbel, enco_theta, enco_gamma, u_adj, out);

    cudaFuncSetAttribute(main_kernel, cudaFuncAttributeMaxDynamicSharedMemorySize, SMEM_BYTES);
    main_kernel<<<GRID_MAIN, 256, SMEM_BYTES>>>(
        z_sample, target, z_mean, z_logstd, z_shared,
        W1, b1, gn1_w, gn1_b, W2, b2, gn2_w, gn2_b, W3, b3, tanh_scale, out);
}

// round 17
// speedup vs baseline: 1.0125x; 1.0055x over previous
#include <cuda_runtime.h>
#include <cuda_fp16.h>
#include <math.h>

#define B_   1024
#define L_   32
#define K_   8
#define G_   8
#define C_   128
#define S_   32
#define GRID_MAIN 296
#define NTILES 64
#define NITEMS (L_ * NTILES)

__device__ unsigned char g_ci[B_ * L_];
__device__ unsigned int g_mask[B_ * G_ * L_];

// ---------- helpers ----------
__device__ __forceinline__ unsigned pack2h(float lo, float hi) {
    unsigned r;
    asm("cvt.rn.f16x2.f32 %0, %1, %2;" : "=r"(r) : "f"(hi), "f"(lo));
    return r;
}
__device__ __forceinline__ __half2 u2h(unsigned u) { return *reinterpret_cast<__half2*>(&u); }
__device__ __forceinline__ unsigned h2u(__half2 h) { return *reinterpret_cast<unsigned*>(&h); }

__device__ __forceinline__ float tanh_fast(float x) {
    float xc = fminf(fmaxf(x, -15.0f), 15.0f);
    float e = __expf(2.0f * xc);
    return __fdividef(e - 1.0f, e + 1.0f);
}

// packed GN + SiLU: v,mu,inv,w,b all f16x2; returns silu((v-mu)*inv*w+b) packed
__device__ __forceinline__ unsigned gnsilu2(unsigned v, unsigned mu2, unsigned inv2,
                                            unsigned w2, unsigned b2) {
    __half2 x = __hsub2(u2h(v), u2h(mu2));
    x = __hmul2(x, u2h(inv2));
    x = __hfma2(x, u2h(w2), u2h(b2));
    __half2 m = __hmul2(x, __float2half2_rn(0.5f));
    unsigned t;
    asm("tanh.approx.f16x2 %0, %1;" : "=r"(t) : "r"(h2u(m)));
    return h2u(__hfma2(m, u2h(t), m));
}
__device__ __forceinline__ void mma_f16(float* c,
    unsigned a0, unsigned a1, unsigned a2, unsigned a3, unsigned b0, unsigned b1) {
    asm("mma.sync.aligned.m16n8k16.row.col.f32.f16.f16.f32 "
        "{%0,%1,%2,%3},{%4,%5,%6,%7},{%8,%9},{%0,%1,%2,%3};"
        : "+f"(c[0]), "+f"(c[1]), "+f"(c[2]), "+f"(c[3])
        : "r"(a0), "r"(a1), "r"(a2), "r"(a3), "r"(b0), "r"(b1));
}
__device__ __forceinline__ float bitf(unsigned m, int j) {
    return (float)((m >> j) & 1u);
}
__device__ __forceinline__ float2 ldg2(const float* p) {
    return __ldg((const float2*)p);
}

// Build the 7 k-block fragment halves for one row (layout per round-12).
__device__ __forceinline__ void build_row(unsigned Mw, bool tfl, int tgt,
                                          const float* zp, const float* zhp,
                                          int d2, unsigned out[7][2]) {
    float2 z0 = ldg2(zp + d2);
    float2 z1 = ldg2(zp + d2 + 8);
    out[0][0] = pack2h(bitf(Mw, d2) * z0.x,      bitf(Mw, d2 + 1) * z0.y);
    out[0][1] = pack2h(bitf(Mw, d2 + 8) * z1.x,  bitf(Mw, d2 + 9) * z1.y);
    float2 z2 = ldg2(zp + d2 + 16);
    float2 z3 = ldg2(zp + d2 + 24);
    out[1][0] = pack2h(bitf(Mw, d2 + 16) * z2.x, bitf(Mw, d2 + 17) * z2.y);
    out[1][1] = pack2h(bitf(Mw, d2 + 24) * z3.x, bitf(Mw, d2 + 25) * z3.y);
    out[2][0] = pack2h(bitf(Mw, d2),      bitf(Mw, d2 + 1));
    out[2][1] = pack2h(bitf(Mw, d2 + 8),  bitf(Mw, d2 + 9));
    out[3][0] = pack2h(bitf(Mw, d2 + 16), bitf(Mw, d2 + 17));
    out[3][1] = pack2h(bitf(Mw, d2 + 24), bitf(Mw, d2 + 25));
    float tv0 = (tfl && tgt == d2)     ? 1.0f : 0.0f;
    float tv1 = (tfl && tgt == d2 + 1) ? 1.0f : 0.0f;
    float2 s0 = ldg2(zhp + d2);
    out[4][0] = pack2h(tv0, tv1);
    out[4][1] = pack2h(s0.x, s0.y);
    float2 s1 = ldg2(zhp + 8 + d2);
    float2 s2 = ldg2(zhp + 16 + d2);
    out[5][0] = pack2h(s1.x, s1.y);
    out[5][1] = pack2h(s2.x, s2.y);
    float2 s3 = ldg2(zhp + 24 + d2);
    out[6][0] = pack2h(s3.x, s3.y);
    out[6][1] = (d2 == 0) ? pack2h(1.0f, 0.0f) : 0u;
}

// ---------- merged prep ----------
__global__ void prep_kernel(const float* __restrict__ tp, const float* __restrict__ ug,
                            const float* __restrict__ th, const float* __restrict__ ga,
                            const float* __restrict__ u_adj, float* __restrict__ out) {
    __shared__ unsigned char sc[L_];
    __shared__ float sep[K_ * K_];
    int b = blockIdx.x, t = threadIdx.x;
    if (t < L_) {
        const float* u = ug + (b * L_ + t) * K_;
        float best = -1e30f; int bi = 0;
#pragma unroll
        for (int k = 0; k < K_; k++) {
            float gum = -logf(-logf(u[k] + 1e-10f) + 1e-10f);
            float v = tp[t * K_ + k] + gum;
            if (v > best) { best = v; bi = k; }
        }
        sc[t] = (unsigned char)bi;
        g_ci[b * L_ + t] = (unsigned char)bi;
    } else if (t >= 64 && t < 128) {
        int e = t - 64;
        float s1 = 1.0f / (1.0f + expf(-th[e]));
        float s2 = 1.0f / (1.0f + expf(-ga[e]));
        sep[e] = s1 * s2;
    }
    if (t == 0) out[b] = 0.0f;
    __syncthreads();
    int g = t >> 5, l = t & 31;
    int cl = sc[l];
    unsigned bits = 0;
#pragma unroll
    for (int cj = 0; cj < K_; cj++) {
        float u = u_adj[((b * G_ + g) * K_ + cj) * K_ + cl];
        bits |= (u < sep[cj * K_ + cl]) ? (1u << cj) : 0u;
    }
    unsigned wv = 0;
#pragma unroll
    for (int j = 0; j < L_; j++) {
        unsigned mj = (bits >> sc[j]) & 1u;
        if (j == l) mj = 0;
        wv |= mj << j;
    }
    g_mask[(b * G_ + g) * L_ + l] = wv;
}

// ---------- smem layout (bytes) ----------
#define OFF_W1    0
#define OFF_W2    40960
#define OFF_WB1H  81920   // uint2[64]: (g1w pair f16x2, g1b pair f16x2)
#define OFF_P2H   82432   // uint2[64]: (g2w pair f16x2, g2b pair f16x2)
#define OFF_B2    82944   // float2[64]: b2 pairs fp32
#define OFF_W3    83456   // float4[64]: (w30_c0, w31_c0, w30_c1, w31_c1)
#define SMEM_BYTES 84480

__global__ __launch_bounds__(256, 2) void main_kernel(
    const float* __restrict__ z_sample, const int* __restrict__ target,
    const float* __restrict__ z_mean,   const float* __restrict__ z_logstd,
    const float* __restrict__ z_shared,
    const float* __restrict__ W1, const float* __restrict__ b1g,
    const float* __restrict__ g1wg, const float* __restrict__ g1bg,
    const float* __restrict__ W2, const float* __restrict__ b2g,
    const float* __restrict__ g2wg, const float* __restrict__ g2bg,
    const float* __restrict__ W3g, const float* __restrict__ b3g,
    const float* __restrict__ tsc, float* __restrict__ out)
{
    extern __shared__ char smem[];
    uint2*  W1u2 = (uint2*)(smem + OFF_W1);
    uint2*  W2u2 = (uint2*)(smem + OFF_W2);
    const uint4* W1q4 = (const uint4*)(smem + OFF_W1);
    const uint4* W2q4 = (const uint4*)(smem + OFF_W2);
    uint2*  sWB1h = (uint2*)(smem + OFF_WB1H);
    uint2*  sP2h  = (uint2*)(smem + OFF_P2H);
    float2* sB2   = (float2*)(smem + OFF_B2);
    float4* sW3   = (float4*)(smem + OFF_W3);

    const int tid = threadIdx.x;
    const int wid = tid >> 5;
    const int lane = tid & 31;
    const int gid = lane >> 2;
    const int t4 = lane & 3;
    const int d2 = t4 * 2;

    const int start = (int)(((long long)blockIdx.x * NITEMS) / GRID_MAIN);
    const int end   = (int)(((long long)(blockIdx.x + 1) * NITEMS) / GRID_MAIN);

    int cur_l = -1;
    float b3_0 = 0.f, b3_1 = 0.f, sc0 = 1.f, sc1 = 1.f, isc0 = 1.f, isc1 = 1.f;

    for (int item = start; item < end; item++) {
        const int l = item >> 6;
        const int tile = item & 63;

        if (l != cur_l) {
            __syncthreads();
            // ---- vectorized W1 staging: unit = (c, kk), kk 0..6 ----
            const float4* W1g4 = (const float4*)(W1 + l * C_ * 104);   // rows are 416B, 16B-aligned
            for (int idx = tid; idx < 128 * 7; idx += 256) {
                int c = idx / 7, kk = idx - c * 7;
                int base = c * 40 + (kk >> 1) * 8 + (kk & 1);
                if (kk < 6) {
                    float4 f0 = W1g4[c * 26 + kk * 4 + 0];
                    float4 f1 = W1g4[c * 26 + kk * 4 + 1];
                    float4 f2 = W1g4[c * 26 + kk * 4 + 2];
                    float4 f3 = W1g4[c * 26 + kk * 4 + 3];
                    W1u2[base + 0] = make_uint2(pack2h(f0.x, f0.y), pack2h(f2.x, f2.y));
                    W1u2[base + 2] = make_uint2(pack2h(f0.z, f0.w), pack2h(f2.z, f2.w));
                    W1u2[base + 4] = make_uint2(pack2h(f1.x, f1.y), pack2h(f3.x, f3.y));
                    W1u2[base + 6] = make_uint2(pack2h(f1.z, f1.w), pack2h(f3.z, f3.w));
                } else {
                    float4 f0 = W1g4[c * 26 + 24];
                    float4 f1 = W1g4[c * 26 + 25];
                    float bias = b1g[l * C_ + c];
                    W1u2[base + 0] = make_uint2(pack2h(f0.x, f0.y), pack2h(bias, 0.0f));
                    W1u2[base + 2] = make_uint2(pack2h(f0.z, f0.w), 0u);
                    W1u2[base + 4] = make_uint2(pack2h(f1.x, f1.y), 0u);
                    W1u2[base + 6] = make_uint2(pack2h(f1.z, f1.w), 0u);
                }
            }
            // ---- vectorized W2 staging: unit = (c, kk), kk 0..7 ----
            const float4* W2g4 = (const float4*)(W2 + l * C_ * C_);
            for (int idx = tid; idx < 128 * 8; idx += 256) {
                int c = idx >> 3, kk = idx & 7;
                int base = c * 40 + (kk >> 1) * 8 + (kk & 1);
                float4 f0 = W2g4[c * 32 + kk * 4 + 0];
                float4 f1 = W2g4[c * 32 + kk * 4 + 1];
                float4 f2 = W2g4[c * 32 + kk * 4 + 2];
                float4 f3 = W2g4[c * 32 + kk * 4 + 3];
                W2u2[base + 0] = make_uint2(pack2h(f0.x, f0.y), pack2h(f2.x, f2.y));
                W2u2[base + 2] = make_uint2(pack2h(f0.z, f0.w), pack2h(f2.z, f2.w));
                W2u2[base + 4] = make_uint2(pack2h(f1.x, f1.y), pack2h(f3.x, f3.y));
                W2u2[base + 6] = make_uint2(pack2h(f1.z, f1.w), pack2h(f3.z, f3.w));
            }
            if (tid < 64) {
                int c0 = 2 * tid;
                sWB1h[tid] = make_uint2(pack2h(g1wg[l * C_ + c0], g1wg[l * C_ + c0 + 1]),
                                        pack2h(g1bg[l * C_ + c0], g1bg[l * C_ + c0 + 1]));
                sP2h[tid]  = make_uint2(pack2h(g2wg[l * C_ + c0], g2wg[l * C_ + c0 + 1]),
                                        pack2h(g2bg[l * C_ + c0], g2bg[l * C_ + c0 + 1]));
                sB2[tid]   = make_float2(b2g[l * C_ + c0], b2g[l * C_ + c0 + 1]);
                sW3[tid]   = make_float4(W3g[l * 2 * C_ + c0],     W3g[l * 2 * C_ + C_ + c0],
                                         W3g[l * 2 * C_ + c0 + 1], W3g[l * 2 * C_ + C_ + c0 + 1]);
            }
            b3_0 = b3g[l * 2]; b3_1 = b3g[l * 2 + 1];
            sc0 = __expf(tsc[l * 2]); sc1 = __expf(tsc[l * 2 + 1]);
            isc0 = 1.0f / sc0; isc1 = 1.0f / sc1;
            __syncthreads();
            cur_l = l;
        }

        // per-thread rows: r0 = wid*16+gid (batch b0), r1 = r0+8 (batch b1)
        const int grow0 = tile * 128 + wid * 16 + gid;
        const int grow1 = grow0 + 8;
        const int b0i = grow0 >> 3, b1i = grow1 >> 3;
        const unsigned Mw0 = __ldg(&g_mask[grow0 * L_ + l]);
        const unsigned Mw1 = __ldg(&g_mask[grow1 * L_ + l]);
        const int tgt0 = __ldg(&target[b0i]), tgt1 = __ldg(&target[b1i]);
        const bool tf0 = (g_ci[b0i * L_ + l] == tgt0);
        const bool tf1 = (g_ci[b1i * L_ + l] == tgt1);

        // ---- build A1 fragments from global (L2-hot) ----
        unsigned Ah[7][4];
        {
            unsigned rA[7][2], rB[7][2];
            build_row(Mw0, tf0, tgt0, z_sample + b0i * L_, z_shared + b0i * S_, d2, rA);
            build_row(Mw1, tf1, tgt1, z_sample + b1i * L_, z_shared + b1i * S_, d2, rB);
#pragma unroll
            for (int kk = 0; kk < 7; kk++) {
                Ah[kk][0] = rA[kk][0];
                Ah[kk][1] = rB[kk][0];
                Ah[kk][2] = rA[kk][1];
                Ah[kk][3] = rB[kk][1];
            }
        }

        // ---- MMA1 (bias folded into W1) ----
        float acc[16][4];
#pragma unroll
        for (int nt = 0; nt < 16; nt++)
#pragma unroll
            for (int i = 0; i < 4; i++) acc[nt][i] = 0.0f;

#pragma unroll
        for (int nt = 0; nt < 16; nt++) {
            const uint4* bp = W1q4 + (nt * 8 + gid) * 20 + t4;
#pragma unroll
            for (int j = 0; j < 4; j++) {
                uint4 bq = bp[j * 4];
                mma_f16(acc[nt], Ah[2*j][0], Ah[2*j][1], Ah[2*j][2], Ah[2*j][3], bq.x, bq.y);
                if (j < 3)
                    mma_f16(acc[nt], Ah[2*j+1][0], Ah[2*j+1][1], Ah[2*j+1][2], Ah[2*j+1][3], bq.z, bq.w);
            }
        }

        // ---- GN1 stats (fp32) ----
        float s0 = 0.f, q0 = 0.f, s1 = 0.f, q1 = 0.f;
#pragma unroll
        for (int nt = 0; nt < 16; nt++) {
            s0 += acc[nt][0] + acc[nt][1];
            q0 += acc[nt][0] * acc[nt][0] + acc[nt][1] * acc[nt][1];
            s1 += acc[nt][2] + acc[nt][3];
            q1 += acc[nt][2] * acc[nt][2] + acc[nt][3] * acc[nt][3];
        }
#pragma unroll
        for (int o = 1; o <= 2; o <<= 1) {
            s0 += __shfl_xor_sync(0xffffffffu, s0, o);
            q0 += __shfl_xor_sync(0xffffffffu, q0, o);
            s1 += __shfl_xor_sync(0xffffffffu, s1, o);
            q1 += __shfl_xor_sync(0xffffffffu, q1, o);
        }
        float mu0 = s0 * (1.0f / 128.0f);
        float inv0 = rsqrtf(q0 * (1.0f / 128.0f) - mu0 * mu0 + 1e-5f);
        float mu1 = s1 * (1.0f / 128.0f);
        float inv1 = rsqrtf(q1 * (1.0f / 128.0f) - mu1 * mu1 + 1e-5f);

        // ---- GN1 + SiLU in packed f16x2 -> A2 fragments ----
        unsigned mu2_0 = pack2h(mu0, mu0), mu2_1 = pack2h(mu1, mu1);
        unsigned iv2_0 = pack2h(inv0, inv0), iv2_1 = pack2h(inv1, inv1);
        unsigned A2h[8][4];
#pragma unroll
        for (int kk = 0; kk < 8; kk++) {
            int nt0 = 2 * kk, nt1 = 2 * kk + 1;
            uint2 wb0 = sWB1h[nt0 * 4 + t4];
            uint2 wb1 = sWB1h[nt1 * 4 + t4];
            A2h[kk][0] = gnsilu2(pack2h(acc[nt0][0], acc[nt0][1]), mu2_0, iv2_0, wb0.x, wb0.y);
            A2h[kk][1] = gnsilu2(pack2h(acc[nt0][2], acc[nt0][3]), mu2_1, iv2_1, wb0.x, wb0.y);
            A2h[kk][2] = gnsilu2(pack2h(acc[nt1][0], acc[nt1][1]), mu2_0, iv2_0, wb1.x, wb1.y);
            A2h[kk][3] = gnsilu2(pack2h(acc[nt1][2], acc[nt1][3]), mu2_1, iv2_1, wb1.x, wb1.y);
        }

        // ---- MMA2 (acc initialized with b2 -> bias add is free) ----
#pragma unroll
        for (int nt = 0; nt < 16; nt++) {
            float2 bb = sB2[nt * 4 + t4];
            acc[nt][0] = bb.x; acc[nt][1] = bb.y;
            acc[nt][2] = bb.x; acc[nt][3] = bb.y;
        }

#pragma unroll
        for (int nt = 0; nt < 16; nt++) {
            const uint4* bp = W2q4 + (nt * 8 + gid) * 20 + t4;
#pragma unroll
            for (int j = 0; j < 4; j++) {
                uint4 bq = bp[j * 4];
                mma_f16(acc[nt], A2h[2*j][0], A2h[2*j][1], A2h[2*j][2], A2h[2*j][3], bq.x, bq.y);
                mma_f16(acc[nt], A2h[2*j+1][0], A2h[2*j+1][1], A2h[2*j+1][2], A2h[2*j+1][3], bq.z, bq.w);
            }
        }

        // ---- GN2 stats (fp32) ----
        s0 = 0.f; q0 = 0.f; s1 = 0.f; q1 = 0.f;
#pragma unroll
        for (int nt = 0; nt < 16; nt++) {
            s0 += acc[nt][0] + acc[nt][1];
            q0 += acc[nt][0] * acc[nt][0] + acc[nt][1] * acc[nt][1];
            s1 += acc[nt][2] + acc[nt][3];
            q1 += acc[nt][2] * acc[nt][2] + acc[nt][3] * acc[nt][3];
        }
#pragma unroll
        for (int o = 1; o <= 2; o <<= 1) {
            s0 += __shfl_xor_sync(0xffffffffu, s0, o);
            q0 += __shfl_xor_sync(0xffffffffu, q0, o);
            s1 += __shfl_xor_sync(0xffffffffu, s1, o);
            q1 += __shfl_xor_sync(0xffffffffu, q1, o);
        }
        mu0 = s0 * (1.0f / 128.0f);
        inv0 = rsqrtf(q0 * (1.0f / 128.0f) - mu0 * mu0 + 1e-5f);
        mu1 = s1 * (1.0f / 128.0f);
        inv1 = rsqrtf(q1 * (1.0f / 128.0f) - mu1 * mu1 + 1e-5f);
        mu2_0 = pack2h(mu0, mu0); mu2_1 = pack2h(mu1, mu1);
        iv2_0 = pack2h(inv0, inv0); iv2_1 = pack2h(inv1, inv1);

        // ---- GN2 + SiLU (f16x2) + W3 dot (fp32) ----
        float p00 = 0.f, p10 = 0.f, p01 = 0.f, p11 = 0.f;
#pragma unroll
        for (int nt = 0; nt < 16; nt++) {
            uint2 wb = sP2h[nt * 4 + t4];
            float4 w3 = sW3[nt * 4 + t4];  // (w30_c0, w31_c0, w30_c1, w31_c1)
            float2 ha = __half22float2(u2h(
                gnsilu2(pack2h(acc[nt][0], acc[nt][1]), mu2_0, iv2_0, wb.x, wb.y)));
            float2 hb = __half22float2(u2h(
                gnsilu2(pack2h(acc[nt][2], acc[nt][3]), mu2_1, iv2_1, wb.x, wb.y)));
            p00 += ha.x * w3.x + ha.y * w3.z;
            p10 += ha.x * w3.y + ha.y * w3.w;
            p01 += hb.x * w3.x + hb.y * w3.z;
            p11 += hb.x * w3.y + hb.y * w3.w;
        }
#pragma unroll
        for (int o = 1; o <= 2; o <<= 1) {
            p00 += __shfl_xor_sync(0xffffffffu, p00, o);
            p10 += __shfl_xor_sync(0xffffffffu, p10, o);
            p01 += __shfl_xor_sync(0xffffffffu, p01, o);
            p11 += __shfl_xor_sync(0xffffffffu, p11, o);
        }

        // ---- KL on all lanes (quad-uniform), reduce over 8 graphs, 1 atomic/b ----
        float kld0, kld1;
        {
            float zl = z_logstd[b0i * L_ + l], zmn = z_mean[b0i * L_ + l];
            float o0 = p00 + b3_0, o1 = p10 + b3_1;
            float pm = tanh_fast(o0 * isc0) * sc0;
            float pl = tanh_fast(o1 * isc1) * sc1;
            float dmu = zmn - pm;
            kld0 = pl - zl + (__expf(2.0f * zl) + dmu * dmu) * 0.5f * __expf(-2.0f * pl) - 0.5f;
        }
        {
            float zl = z_logstd[b1i * L_ + l], zmn = z_mean[b1i * L_ + l];
            float o0 = p01 + b3_0, o1 = p11 + b3_1;
            float pm = tanh_fast(o0 * isc0) * sc0;
            float pl = tanh_fast(o1 * isc1) * sc1;
            float dmu = zmn - pm;
            kld1 = pl - zl + (__expf(2.0f * zl) + dmu * dmu) * 0.5f * __expf(-2.0f * pl) - 0.5f;
        }
#pragma unroll
        for (int o = 4; o <= 16; o <<= 1) {
            kld0 += __shfl_xor_sync(0xffffffffu, kld0, o);
            kld1 += __shfl_xor_sync(0xffffffffu, kld1, o);
        }
        if (lane == 0) {
            atomicAdd(out + b0i, kld0 * 0.125f);
            atomicAdd(out + b1i, kld1 * 0.125f);
        }
    }
}

extern "C" void kernel_launch(void* const* d_in, const int* in_sizes, int n_in,
                              void* d_out, int out_size) {
    const float* z_sample      = (const float*)d_in[0];
    const int*   target        = (const int*)  d_in[1];
    const float* z_mean        = (const float*)d_in[2];
    const float* z_logstd      = (const float*)d_in[3];
    const float* z_shared      = (const float*)d_in[4];
    const float* u_gumbel      = (const float*)d_in[5];
    const float* u_adj         = (const float*)d_in[6];
    const float* target_params = (const float*)d_in[7];
    const float* enco_theta    = (const float*)d_in[8];
    const float* enco_gamma    = (const float*)d_in[9];
    const float* W1            = (const float*)d_in[10];
    const float* b1            = (const float*)d_in[11];
    const float* gn1_w         = (const float*)d_in[12];
    const float* gn1_b         = (const float*)d_in[13];
    const float* W2            = (const float*)d_in[14];
    const float* b2            = (const float*)d_in[15];
    const float* gn2_w         = (const float*)d_in[16];
    const float* gn2_b         = (const float*)d_in[17];
    const float* W3            = (const float*)d_in[18];
    const float* b3            = (const float*)d_in[19];
    const float* tanh_scale    = (const float*)d_in[20];
    float* out = (float*)d_out;

    prep_kernel<<<B_, 256>>>(target_params, u_gumbel, enco_theta, enco_gamma, u_adj, out);

    cudaFuncSetAttribute(main_kernel, cudaFuncAttributeMaxDynamicSharedMemorySize, SMEM_BYTES);
    main_kernel<<<GRID_MAIN, 256, SMEM_BYTES>>>(
        z_sample, target, z_mean, z_logstd, z_shared,
        W1, b1, gn1_w, gn1_b, W2, b2, gn2_w, gn2_b, W3, b3, tanh_scale, out);
}